// round 2
// baseline (speedup 1.0000x reference)
#include <cuda_runtime.h>

// out[b,h,i,j] = scores[b,h,i,j] + sum_d q[b,h,i,d] * emb[j - i + 4096, d]
// Shapes: q [32, 2048, 64], scores/out [32, 2048, 2048], emb [8192, 64], all fp32.

#define S_LEN 2048
#define D_HEAD 64
#define N_BH 32
#define TI 32
#define TJ 128
#define WIN (TI + TJ - 1)   // 159 rel_emb rows per block
#define EROWS 160           // padded (keeps float4 reads in-bounds)
#define HALF_EMB 4096

// SMEM: Es 64*160*4 = 40960 B, Qs 64*32*4 = 8192 B -> 49152 B total
__global__ __launch_bounds__(128, 4)
void relpos_bias_kernel(const float* __restrict__ q,
                        const float* __restrict__ scores,
                        const float* __restrict__ emb,
                        float* __restrict__ out)
{
    __shared__ float Es[D_HEAD][EROWS];  // transposed: Es[d][local_row]
    __shared__ float Qs[D_HEAD][TI];     // transposed: Qs[d][local_i]

    const int bh = blockIdx.z;
    const int i0 = blockIdx.y * TI;
    const int j0 = blockIdx.x * TJ;
    const int tid = threadIdx.x;
    // Micro-tile: 8(i) x 4(j) per thread. tx spans a full warp -> E LDS base
    // stride is 4 words/lane -> 8 lanes/phase cover 32 distinct banks
    // (conflict-free); ty is warp-uniform -> Q LDS are broadcasts.
    const int tx = tid & 31;   // 32 threads along j, 4 cols each
    const int ty = tid >> 5;   // 4 threads along i, 8 rows each

    // ---- Load Q tile [TI x D] -> transposed SMEM ----
    const float* qbase = q + ((size_t)bh * S_LEN + i0) * D_HEAD;
    #pragma unroll
    for (int k = tid; k < TI * (D_HEAD / 4); k += 128) {
        int row = k >> 4;          // local i
        int c4  = k & 15;          // which float4 along d
        float4 v = reinterpret_cast<const float4*>(qbase + (size_t)row * D_HEAD)[c4];
        int d = c4 * 4;
        Qs[d + 0][row] = v.x; Qs[d + 1][row] = v.y;
        Qs[d + 2][row] = v.z; Qs[d + 3][row] = v.w;
    }

    // ---- Load rel_emb window [WIN x D] -> transposed SMEM ----
    // global emb row for local (ii,jj): (j0+jj) - (i0+ii) + 4096 = e0 + (jj - ii + TI-1)
    const int e0 = j0 - i0 + HALF_EMB - (TI - 1);   // always in [2049, 6017]
    const float* ebase = emb + (size_t)e0 * D_HEAD;
    for (int k = tid; k < WIN * (D_HEAD / 4); k += 128) {
        int row = k >> 4;
        int c4  = k & 15;
        float4 v = reinterpret_cast<const float4*>(ebase + (size_t)row * D_HEAD)[c4];
        int d = c4 * 4;
        Es[d + 0][row] = v.x; Es[d + 1][row] = v.y;
        Es[d + 2][row] = v.z; Es[d + 3][row] = v.w;
    }
    __syncthreads();

    // ---- Main loop: 8(i) x 4(j) micro-tile per thread ----
    float acc[8][4];
    #pragma unroll
    for (int a = 0; a < 8; a++)
        #pragma unroll
        for (int b = 0; b < 4; b++) acc[a][b] = 0.0f;

    // local E row for (a,b): (tx*4+b) - (ty*8+a) + (TI-1) = base + (b - a + 7)
    const int base = tx * 4 - ty * 8 + (TI - 8);   // multiple of 4, in [0, 148]

    #pragma unroll 8
    for (int d = 0; d < D_HEAD; d++) {
        float4 qv0 = *reinterpret_cast<const float4*>(&Qs[d][ty * 8]);
        float4 qv1 = *reinterpret_cast<const float4*>(&Qs[d][ty * 8 + 4]);
        float4 ea = *reinterpret_cast<const float4*>(&Es[d][base]);
        float4 eb = *reinterpret_cast<const float4*>(&Es[d][base + 4]);
        float4 ec = *reinterpret_cast<const float4*>(&Es[d][base + 8]);
        float ev[12] = { ea.x, ea.y, ea.z, ea.w,
                         eb.x, eb.y, eb.z, eb.w,
                         ec.x, ec.y, ec.z, ec.w };
        float qq[8] = { qv0.x, qv0.y, qv0.z, qv0.w,
                        qv1.x, qv1.y, qv1.z, qv1.w };
        #pragma unroll
        for (int a = 0; a < 8; a++)
            #pragma unroll
            for (int b = 0; b < 4; b++)
                acc[a][b] = fmaf(qq[a], ev[b - a + 7], acc[a][b]);
    }

    // ---- Epilogue: out = scores + acc (warp writes 512B contiguous/row) ----
    #pragma unroll
    for (int a = 0; a < 8; a++) {
        size_t off = ((size_t)bh * S_LEN + (size_t)(i0 + ty * 8 + a)) * S_LEN
                   + (size_t)(j0 + tx * 4);
        float4 s = *reinterpret_cast<const float4*>(scores + off);
        float4 o = make_float4(s.x + acc[a][0], s.y + acc[a][1],
                               s.z + acc[a][2], s.w + acc[a][3]);
        *reinterpret_cast<float4*>(out + off) = o;
    }
}

extern "C" void kernel_launch(void* const* d_in, const int* in_sizes, int n_in,
                              void* d_out, int out_size)
{
    const float* q      = (const float*)d_in[0];  // [2,16,2048,64]
    const float* scores = (const float*)d_in[1];  // [2,16,2048,2048]
    const float* emb    = (const float*)d_in[2];  // [8192,64]
    float* out = (float*)d_out;

    dim3 grid(S_LEN / TJ, S_LEN / TI, N_BH);   // (16, 64, 32)
    relpos_bias_kernel<<<grid, 128>>>(q, scores, emb, out);
}

// round 4
// speedup vs baseline: 3.4435x; 3.4435x over previous
#include <cuda_runtime.h>
#include <cuda_bf16.h>
#include <cstdint>

// out[b,h,i,j] = scores[b,h,i,j] + sum_d q[b,h,i,d] * emb[j-i+4096, d]
// Per 64(i) x 128(j) tile: G[64 x 192] = Q_tile @ E_window^T as bf16 hi/lo
// 3-pass mma.sync GEMM (fp32-accurate), then skewed band add via SMEM.

#define S_LEN 2048
#define D_HEAD 64
#define TI 64
#define TJ 128
#define NB 192          // padded window (191 needed)
#define HALF 4096
#define GS 197          // G staging stride in words (== 1 mod 4)

#define OFF_QH 0        // 64 x 128B  (bf16 hi, XOR-swizzled rows)
#define OFF_QL 8192
#define OFF_EH 16384    // 192 x 128B
#define OFF_EL 40960
#define SMEM_TOTAL 65536
// G staging (64 x GS words fp32, 50432 B) reuses [0, 65536) after compute.

static __device__ __forceinline__ uint32_t smem_u32(const void* p) {
    uint32_t a;
    asm("{ .reg .u64 t; cvta.to.shared.u64 t, %1; cvt.u32.u64 %0, t; }"
        : "=r"(a) : "l"(p));
    return a;
}
static __device__ __forceinline__ uint32_t pack_bf16(float x, float y) {
    return (uint32_t)__bfloat16_as_ushort(__float2bfloat16_rn(x)) |
           ((uint32_t)__bfloat16_as_ushort(__float2bfloat16_rn(y)) << 16);
}

// Convert float4 -> hi(2xb32) + lo(2xb32) and store to two swizzled rows.
static __device__ __forceinline__ void store_hilo(uint32_t hi_addr, uint32_t lo_addr,
                                                  float4 v) {
    float hx = __bfloat162float(__float2bfloat16_rn(v.x));
    float hy = __bfloat162float(__float2bfloat16_rn(v.y));
    float hz = __bfloat162float(__float2bfloat16_rn(v.z));
    float hw = __bfloat162float(__float2bfloat16_rn(v.w));
    uint32_t h01 = pack_bf16(v.x, v.y), h23 = pack_bf16(v.z, v.w);
    uint32_t l01 = pack_bf16(v.x - hx, v.y - hy), l23 = pack_bf16(v.z - hz, v.w - hw);
    asm volatile("st.shared.v2.b32 [%0], {%1,%2};" :: "r"(hi_addr), "r"(h01), "r"(h23) : "memory");
    asm volatile("st.shared.v2.b32 [%0], {%1,%2};" :: "r"(lo_addr), "r"(l01), "r"(l23) : "memory");
}

__global__ __launch_bounds__(256)
void relpos_mma_kernel(const float* __restrict__ q,
                       const float* __restrict__ scores,
                       const float* __restrict__ emb,
                       float* __restrict__ out)
{
    extern __shared__ char smem[];
    const uint32_t sb = smem_u32(smem);
    const int tid = threadIdx.x, wid = tid >> 5, lane = tid & 31;
    const int bh = blockIdx.z, i0 = blockIdx.y * TI, j0 = blockIdx.x * TJ;

    // ---- Load + convert Q [64 x 64] -> Qhi/Qlo, rows 128B, 16B-chunk XOR swizzle ----
    {
        const float* qb = q + ((size_t)bh * S_LEN + i0) * D_HEAD;
        #pragma unroll
        for (int it = 0; it < 4; it++) {
            int u = it * 256 + tid;                 // 1024 units
            int row = u >> 4, g = u & 15;           // g: 8B granule (4 floats)
            float4 v = __ldg((const float4*)(qb + (size_t)row * D_HEAD) + g);
            uint32_t off = (uint32_t)(row * 128 + (((g >> 1) ^ (row & 7)) << 4) + (g & 1) * 8);
            store_hilo(sb + OFF_QH + off, sb + OFF_QL + off, v);
        }
    }
    // ---- Load + convert E window [192 x 64] -> Ehi/Elo ----
    {
        const int e0 = j0 - i0 + HALF - (TI - 1);   // in [2049, 6017]; rows e0..e0+191 valid
        const float* eb = emb + (size_t)e0 * D_HEAD;
        #pragma unroll
        for (int it = 0; it < 12; it++) {
            int u = it * 256 + tid;                 // 3072 units
            int row = u >> 4, g = u & 15;
            float4 v = __ldg((const float4*)(eb + (size_t)row * D_HEAD) + g);
            uint32_t off = (uint32_t)(row * 128 + (((g >> 1) ^ (row & 7)) << 4) + (g & 1) * 8);
            store_hilo(sb + OFF_EH + off, sb + OFF_EL + off, v);
        }
    }
    __syncthreads();

    // ---- GEMM: warp (mg, nh) computes rows [16mg,16mg+16) x cols [96nh,96nh+96) ----
    const int mg = wid >> 1, nh = wid & 1;
    const int m0 = mg * 16, n0 = nh * 96;
    float c[12][4];
    #pragma unroll
    for (int f = 0; f < 12; f++)
        #pragma unroll
        for (int k = 0; k < 4; k++) c[f][k] = 0.0f;

    // A ldmatrix lane addressing (row-major 16x16, tiles m0-7/k0-7, m8-15/k0-7, m0-7/k8-15, m8-15/k8-15)
    const int a_row = m0 + (lane & 7) + ((lane >> 3) & 1) * 8;
    const int a_ch  = (lane >> 4);        // + 2*ks
    // B ldmatrix lane addressing (two n-frags per x4)
    const int b_rl  = (lane & 7);
    const int b_nf  = (lane >> 4);        // 0 -> nf, 1 -> nf+1
    const int b_ch  = (lane >> 3) & 1;    // + 2*ks

    #pragma unroll
    for (int pass = 0; pass < 3; pass++) {
        const uint32_t Ab = sb + (pass < 2 ? OFF_QH : OFF_QL);
        const uint32_t Bb = sb + (pass == 1 ? OFF_EL : OFF_EH);
        #pragma unroll
        for (int ks = 0; ks < 4; ks++) {
            uint32_t a0, a1, a2, a3;
            {
                int ch = (2 * ks + a_ch) ^ (a_row & 7);
                uint32_t addr = Ab + (uint32_t)(a_row * 128 + ch * 16);
                asm volatile("ldmatrix.sync.aligned.m8n8.x4.shared.b16 {%0,%1,%2,%3}, [%4];"
                             : "=r"(a0), "=r"(a1), "=r"(a2), "=r"(a3) : "r"(addr));
            }
            #pragma unroll
            for (int nf = 0; nf < 12; nf += 2) {
                int nrow = n0 + (nf + b_nf) * 8 + b_rl;
                int ch = (2 * ks + b_ch) ^ (nrow & 7);
                uint32_t addr = Bb + (uint32_t)(nrow * 128 + ch * 16);
                uint32_t b0, b1, b2, b3;
                asm volatile("ldmatrix.sync.aligned.m8n8.x4.shared.b16 {%0,%1,%2,%3}, [%4];"
                             : "=r"(b0), "=r"(b1), "=r"(b2), "=r"(b3) : "r"(addr));
                asm volatile("mma.sync.aligned.m16n8k16.row.col.f32.bf16.bf16.f32 "
                             "{%0,%1,%2,%3}, {%4,%5,%6,%7}, {%8,%9}, {%0,%1,%2,%3};"
                             : "+f"(c[nf][0]), "+f"(c[nf][1]), "+f"(c[nf][2]), "+f"(c[nf][3])
                             : "r"(a0), "r"(a1), "r"(a2), "r"(a3), "r"(b0), "r"(b1));
                asm volatile("mma.sync.aligned.m16n8k16.row.col.f32.bf16.bf16.f32 "
                             "{%0,%1,%2,%3}, {%4,%5,%6,%7}, {%8,%9}, {%0,%1,%2,%3};"
                             : "+f"(c[nf+1][0]), "+f"(c[nf+1][1]), "+f"(c[nf+1][2]), "+f"(c[nf+1][3])
                             : "r"(a0), "r"(a1), "r"(a2), "r"(a3), "r"(b2), "r"(b3));
            }
        }
    }
    __syncthreads();   // all HMMA reads of operand SMEM done -> safe to overwrite

    // ---- Stage G to skewed SMEM: word(row,col) = row*GS + 1 + col ----
    {
        const int r0 = m0 + (lane >> 2);
        #pragma unroll
        for (int nf = 0; nf < 12; nf++) {
            int col = n0 + nf * 8 + 2 * (lane & 3);
            uint32_t w0 = sb + (uint32_t)(((r0)     * GS + 1 + col) << 2);
            uint32_t w1 = sb + (uint32_t)(((r0 + 8) * GS + 1 + col) << 2);
            asm volatile("st.shared.b32 [%0], %1;" :: "r"(w0),     "f"(c[nf][0]) : "memory");
            asm volatile("st.shared.b32 [%0], %1;" :: "r"(w0 + 4), "f"(c[nf][1]) : "memory");
            asm volatile("st.shared.b32 [%0], %1;" :: "r"(w1),     "f"(c[nf][2]) : "memory");
            asm volatile("st.shared.b32 [%0], %1;" :: "r"(w1 + 4), "f"(c[nf][3]) : "memory");
        }
    }
    __syncthreads();

    // ---- Combine: out[row][jj] = scores[row][jj] + G[row][jj - row + 63] ----
    // G word base for row: row*GS + 1 + (63 - row) + jj = row*(GS-1) + 64 + jj
    {
        const float* Gw = (const float*)smem;
        const size_t srow = (size_t)bh * S_LEN + (size_t)i0;
        #pragma unroll
        for (int rr = 0; rr < 8; rr++) {
            int row = wid * 8 + rr;
            size_t off = (srow + row) * S_LEN + (size_t)(j0 + 4 * lane);
            float4 s = __ldg((const float4*)(scores + off));
            float4 g = *(const float4*)(Gw + row * (GS - 1) + 64 + 4 * lane);
            float4 o = make_float4(s.x + g.x, s.y + g.y, s.z + g.z, s.w + g.w);
            *(float4*)(out + off) = o;
        }
    }
}

extern "C" void kernel_launch(void* const* d_in, const int* in_sizes, int n_in,
                              void* d_out, int out_size)
{
    const float* q      = (const float*)d_in[0];  // [2,16,2048,64]
    const float* scores = (const float*)d_in[1];  // [2,16,2048,2048]
    const float* emb    = (const float*)d_in[2];  // [8192,64]
    float* out = (float*)d_out;

    cudaFuncSetAttribute(relpos_mma_kernel,
                         cudaFuncAttributeMaxDynamicSharedMemorySize, SMEM_TOTAL);
    dim3 grid(S_LEN / TJ, S_LEN / TI, 32);   // (16, 32, 32) = 16384 CTAs
    relpos_mma_kernel<<<grid, 256, SMEM_TOTAL>>>(q, scores, emb, out);
}

// round 5
// speedup vs baseline: 3.9623x; 1.1506x over previous
#include <cuda_runtime.h>
#include <cuda_bf16.h>
#include <cstdint>

// out[b,h,i,j] = scores[b,h,i,j] + sum_d q[b,h,i,d] * emb[j-i+4096, d]
// Per 64(i) x 256(j) tile: G[64 x 320] = Q_tile @ E_window^T as bf16 hi/lo
// 3-pass mma.sync GEMM (fp32-accurate), then skewed band add via SMEM.

#define S_LEN 2048
#define D_HEAD 64
#define TI 64
#define TJ 256
#define NB 320          // padded window (319 needed)
#define HALF 4096
#define GS 333          // staging stride (words): ==1 mod 4 (aligned LDS.128),
                        // ==13 mod 16 -> STS lane map 13r+2c bijective mod 32

#define OFF_QH 0        // 64 x 128B  (bf16 hi, XOR-swizzled 16B chunks)
#define OFF_QL 8192
#define OFF_EH 16384    // 320 x 128B
#define OFF_EL 57344
#define SMEM_TOTAL 98304
// G staging (64 x GS words fp32, 85248 B) reuses [0, SMEM_TOTAL) after compute.

static __device__ __forceinline__ uint32_t smem_u32(const void* p) {
    uint32_t a;
    asm("{ .reg .u64 t; cvta.to.shared.u64 t, %1; cvt.u32.u64 %0, t; }"
        : "=r"(a) : "l"(p));
    return a;
}
static __device__ __forceinline__ uint32_t pack_bf16(float x, float y) {
    return (uint32_t)__bfloat16_as_ushort(__float2bfloat16_rn(x)) |
           ((uint32_t)__bfloat16_as_ushort(__float2bfloat16_rn(y)) << 16);
}
static __device__ __forceinline__ void store_hilo(uint32_t hi_addr, uint32_t lo_addr,
                                                  float4 v) {
    float hx = __bfloat162float(__float2bfloat16_rn(v.x));
    float hy = __bfloat162float(__float2bfloat16_rn(v.y));
    float hz = __bfloat162float(__float2bfloat16_rn(v.z));
    float hw = __bfloat162float(__float2bfloat16_rn(v.w));
    uint32_t h01 = pack_bf16(v.x, v.y), h23 = pack_bf16(v.z, v.w);
    uint32_t l01 = pack_bf16(v.x - hx, v.y - hy), l23 = pack_bf16(v.z - hz, v.w - hw);
    asm volatile("st.shared.v2.b32 [%0], {%1,%2};" :: "r"(hi_addr), "r"(h01), "r"(h23) : "memory");
    asm volatile("st.shared.v2.b32 [%0], {%1,%2};" :: "r"(lo_addr), "r"(l01), "r"(l23) : "memory");
}

__global__ __launch_bounds__(256, 2)
void relpos_mma2_kernel(const float* __restrict__ q,
                        const float* __restrict__ scores,
                        const float* __restrict__ emb,
                        float* __restrict__ out)
{
    extern __shared__ char smem[];
    const uint32_t sb = smem_u32(smem);
    const int tid = threadIdx.x, wid = tid >> 5, lane = tid & 31;
    const int bh = blockIdx.z, i0 = blockIdx.y * TI, j0 = blockIdx.x * TJ;

    // ---- Load + convert Q [64 x 64] -> Qhi/Qlo ----
    {
        const float* qb = q + ((size_t)bh * S_LEN + i0) * D_HEAD;
        #pragma unroll
        for (int it = 0; it < 4; it++) {
            int u = it * 256 + tid;
            int row = u >> 4, g = u & 15;
            float4 v = __ldg((const float4*)(qb + (size_t)row * D_HEAD) + g);
            uint32_t off = (uint32_t)(row * 128 + (((g >> 1) ^ (row & 7)) << 4) + (g & 1) * 8);
            store_hilo(sb + OFF_QH + off, sb + OFF_QL + off, v);
        }
    }
    // ---- Load + convert E window [320 x 64] -> Ehi/Elo ----
    {
        const int e0 = j0 - i0 + HALF - (TI - 1);   // in [2049, 5825]; +319 stays in-bounds
        const float* eb = emb + (size_t)e0 * D_HEAD;
        #pragma unroll
        for (int it = 0; it < 20; it++) {
            int u = it * 256 + tid;
            int row = u >> 4, g = u & 15;
            float4 v = __ldg((const float4*)(eb + (size_t)row * D_HEAD) + g);
            uint32_t off = (uint32_t)(row * 128 + (((g >> 1) ^ (row & 7)) << 4) + (g & 1) * 8);
            store_hilo(sb + OFF_EH + off, sb + OFF_EL + off, v);
        }
    }
    __syncthreads();

    // ---- GEMM: warp (mg, nh) -> rows [32mg, +32) x cols [80nh, +80) ----
    const int mg = wid >> 2, nh = wid & 3;
    const int m0 = mg * 32, n0 = nh * 80;
    float c[2][10][4];
    #pragma unroll
    for (int mf = 0; mf < 2; mf++)
        #pragma unroll
        for (int f = 0; f < 10; f++)
            #pragma unroll
            for (int k = 0; k < 4; k++) c[mf][f][k] = 0.0f;

    const int a_rl = (lane & 7) + ((lane >> 3) & 1) * 8;
    const int a_ch = lane >> 4;
    const int b_rl = lane & 7;
    const int b_nf = lane >> 4;
    const int b_ch = (lane >> 3) & 1;

    #pragma unroll 1
    for (int pass = 0; pass < 3; pass++) {
        const uint32_t Ab = sb + (pass < 2 ? OFF_QH : OFF_QL);
        const uint32_t Bb = sb + (pass == 1 ? OFF_EL : OFF_EH);
        #pragma unroll
        for (int ks = 0; ks < 4; ks++) {
            uint32_t a[2][4];
            #pragma unroll
            for (int mf = 0; mf < 2; mf++) {
                int row = m0 + mf * 16 + a_rl;
                int ch = (2 * ks + a_ch) ^ (row & 7);
                uint32_t addr = Ab + (uint32_t)(row * 128 + ch * 16);
                asm volatile("ldmatrix.sync.aligned.m8n8.x4.shared.b16 {%0,%1,%2,%3}, [%4];"
                             : "=r"(a[mf][0]), "=r"(a[mf][1]), "=r"(a[mf][2]), "=r"(a[mf][3])
                             : "r"(addr));
            }
            #pragma unroll
            for (int bp = 0; bp < 5; bp++) {
                int nrow = n0 + (2 * bp + b_nf) * 8 + b_rl;
                int ch = (2 * ks + b_ch) ^ (nrow & 7);
                uint32_t addr = Bb + (uint32_t)(nrow * 128 + ch * 16);
                uint32_t b0, b1, b2, b3;
                asm volatile("ldmatrix.sync.aligned.m8n8.x4.shared.b16 {%0,%1,%2,%3}, [%4];"
                             : "=r"(b0), "=r"(b1), "=r"(b2), "=r"(b3) : "r"(addr));
                #pragma unroll
                for (int mf = 0; mf < 2; mf++) {
                    asm volatile("mma.sync.aligned.m16n8k16.row.col.f32.bf16.bf16.f32 "
                                 "{%0,%1,%2,%3}, {%4,%5,%6,%7}, {%8,%9}, {%0,%1,%2,%3};"
                                 : "+f"(c[mf][2*bp][0]), "+f"(c[mf][2*bp][1]),
                                   "+f"(c[mf][2*bp][2]), "+f"(c[mf][2*bp][3])
                                 : "r"(a[mf][0]), "r"(a[mf][1]), "r"(a[mf][2]), "r"(a[mf][3]),
                                   "r"(b0), "r"(b1));
                    asm volatile("mma.sync.aligned.m16n8k16.row.col.f32.bf16.bf16.f32 "
                                 "{%0,%1,%2,%3}, {%4,%5,%6,%7}, {%8,%9}, {%0,%1,%2,%3};"
                                 : "+f"(c[mf][2*bp+1][0]), "+f"(c[mf][2*bp+1][1]),
                                   "+f"(c[mf][2*bp+1][2]), "+f"(c[mf][2*bp+1][3])
                                 : "r"(a[mf][0]), "r"(a[mf][1]), "r"(a[mf][2]), "r"(a[mf][3]),
                                   "r"(b2), "r"(b3));
                }
            }
        }
    }
    __syncthreads();   // operand SMEM reads done -> safe to overwrite with G

    // ---- Stage G to skewed SMEM: word(row,col) = row*GS + 1 + col ----
    {
        #pragma unroll
        for (int mf = 0; mf < 2; mf++) {
            int r0 = m0 + mf * 16 + (lane >> 2);
            #pragma unroll
            for (int nf = 0; nf < 10; nf++) {
                int col = n0 + nf * 8 + 2 * (lane & 3);
                uint32_t w0 = sb + (uint32_t)((r0 * GS + 1 + col) << 2);
                uint32_t w1 = w0 + (uint32_t)(8 * GS * 4);
                asm volatile("st.shared.b32 [%0], %1;" :: "r"(w0),     "f"(c[mf][nf][0]) : "memory");
                asm volatile("st.shared.b32 [%0], %1;" :: "r"(w0 + 4), "f"(c[mf][nf][1]) : "memory");
                asm volatile("st.shared.b32 [%0], %1;" :: "r"(w1),     "f"(c[mf][nf][2]) : "memory");
                asm volatile("st.shared.b32 [%0], %1;" :: "r"(w1 + 4), "f"(c[mf][nf][3]) : "memory");
            }
        }
    }
    __syncthreads();

    // ---- Combine: out[row][jj] = scores[row][jj] + G[row][jj - row + 63] ----
    // staged word = row*(GS-1) + 64 + jj  (aligned float4 since GS-1 % 4 == 0)
    {
        const float* Gw = (const float*)smem;
        const size_t srow = (size_t)bh * S_LEN + (size_t)i0;
        #pragma unroll
        for (int rr = 0; rr < 8; rr++) {
            int row = wid * 8 + rr;
            const float* gr = Gw + row * (GS - 1) + 64;
            size_t off = (srow + row) * S_LEN + (size_t)j0 + 4 * lane;
            #pragma unroll
            for (int h = 0; h < 2; h++) {
                int jj = h * 128 + 4 * lane;
                float4 s = __ldg((const float4*)(scores + off + h * 128));
                float4 g = *(const float4*)(gr + jj);
                float4 o = make_float4(s.x + g.x, s.y + g.y, s.z + g.z, s.w + g.w);
                *(float4*)(out + off + h * 128) = o;
            }
        }
    }
}

extern "C" void kernel_launch(void* const* d_in, const int* in_sizes, int n_in,
                              void* d_out, int out_size)
{
    const float* q      = (const float*)d_in[0];  // [2,16,2048,64]
    const float* scores = (const float*)d_in[1];  // [2,16,2048,2048]
    const float* emb    = (const float*)d_in[2];  // [8192,64]
    float* out = (float*)d_out;

    cudaFuncSetAttribute(relpos_mma2_kernel,
                         cudaFuncAttributeMaxDynamicSharedMemorySize, SMEM_TOTAL);
    dim3 grid(S_LEN / TJ, S_LEN / TI, 32);   // (8, 32, 32) = 8192 CTAs
    relpos_mma2_kernel<<<grid, 256, SMEM_TOTAL>>>(q, scores, emb, out);
}